// round 13
// baseline (speedup 1.0000x reference)
#include <cuda_runtime.h>
#include <cuda_fp16.h>

#define THREADS 512
#define WARPS 16
#define GRID 148
#define TILE_ROWS 32
#define SSR 36              // staging row stride in u32: bank(36g+q)=4g+q -> conflict-free frag reads

// ---- smem layout ----
// Weight region (u32 units): entry ((kt*TN+nt)*32+lane)*2+r packs f16x2 (RN fp16 of w)
// for the B-frag of mma.m16n8k16.
#define OFF_WSYM 0            // TK=1 TN=4 : 256
#define OFF_WIN  512          // TK=3 TN=8 : 1536  (rows permuted: [sym32|x10|pad6])
#define OFF_W1   3584         // TK=4 TN=8 : 2048 each, stride 4096 (x3)
#define OFF_WHD  15872        // heads combined Wr1(nt0..3)+Wc1(nt4..7): TK=4 TN=8 : 2048
// bias region (float units)
#define OFF_BSYM 19968
#define OFF_BIN  20000
#define OFF_B1   20064        // 64*3
#define OFF_BR1  20256
#define OFF_WR2  20288
#define OFF_BC1  20320
#define OFF_WC2  20352        // 32x4
#define OFF_BC2  20480
#define OFF_BR2  20484
#define OFF_STAGE 20488       // u32/float offset; per-warp 32 rows * 36 u32
#define STAGE_U32_PER_WARP (TILE_ROWS * SSR)   // 1152
#define SMEM_FLOATS (OFF_STAGE + WARPS * STAGE_U32_PER_WARP)
#define SMEM_BYTES (SMEM_FLOATS * 4)

// branchless f32 ELU (heads only)
__device__ __forceinline__ float elu_f(float v) {
    float e = __expf(v) - 1.0f;
    return v > 0.0f ? v : e;
}

__device__ __forceinline__ void mma_f16(float* c, const unsigned* a, unsigned b0, unsigned b1) {
    asm volatile(
        "mma.sync.aligned.m16n8k16.row.col.f32.f16.f16.f32 "
        "{%0,%1,%2,%3},{%4,%5,%6,%7},{%8,%9},{%0,%1,%2,%3};\n"
        : "+f"(c[0]), "+f"(c[1]), "+f"(c[2]), "+f"(c[3])
        : "r"(a[0]), "r"(a[1]), "r"(a[2]), "r"(a[3]), "r"(b0), "r"(b1));
}

// Pack two floats into f16x2 (RN). Low half = x (first k).
__device__ __forceinline__ unsigned pack_f16(float x, float y) {
    unsigned r;
    asm("cvt.rn.f16x2.f32 %0, %1, %2;" : "=r"(r) : "f"(y), "f"(x));
    return r;
}

// Packed half2 ELU: elu(v) = max(v,0) + min(exp(v)-1, 0).
// Overflow-safe: v large + -> exp=inf, min(inf-1,0)=0; v large - -> exp=0, min(-1,0)=-1.
__device__ __forceinline__ unsigned elu_h2(unsigned vu) {
    __half2 v = *reinterpret_cast<__half2*>(&vu);
    __half2 e = h2exp(v);
    const __half2 m1 = __float2half2_rn(-1.0f);
    const __half2 z  = __float2half2_rn(0.0f);
    __half2 r = __hadd2(__hmax2(v, z), __hmin2(__hadd2(e, m1), z));
    return *reinterpret_cast<unsigned*>(&r);
}

// 1-term MMA step: C += A * B (single RN-fp16 weight term)
__device__ __forceinline__ void mma1(float* c, const unsigned* a,
                                     const unsigned* W, int idx) {
    uint2 b = *(const uint2*)(W + idx);
    mma_f16(c, a, b.x, b.y);
}

// Init accumulator quad with bias pair (b.x->cols 2q, b.y->cols 2q+1, both row groups).
__device__ __forceinline__ void initC(float* c, float2 b) {
    c[0] = b.x; c[1] = b.y; c[2] = b.x; c[3] = b.y;
}

// Stage W[K,N] row-major -> permuted packed-f16 B-frag layout (RN fp16), zero-padded.
// perm=1: W_in row remap (dst feature order [sym_enc(32)|x(10)|pad(6)]).
__device__ void stage_w(unsigned* dst, const float* __restrict__ src,
                        int K, int N, int TK, int TN_dst, int srcT, int nt_off, int perm) {
    int total = TK * srcT * 64;
    for (int i = threadIdx.x; i < total; i += THREADS) {
        int r = i & 1, lane = (i >> 1) & 31, t = i >> 6;
        int kt = t / srcT, ntl = t % srcT;
        int q = lane & 3, g = lane >> 2;
        int k0 = kt * 16 + r * 8 + 2 * q;
        int n = ntl * 8 + g;
        float w0 = 0.0f, w1 = 0.0f;
        if (n < N) {
            int k = perm ? ((k0 < 32) ? k0 + 10 : (k0 < 42 ? k0 - 32 : -1))
                         : (k0 < K ? k0 : -1);
            if (k >= 0) w0 = src[k * N + n];
            int k1 = k0 + 1;
            k = perm ? ((k1 < 32) ? k1 + 10 : (k1 < 42 ? k1 - 32 : -1))
                     : (k1 < K ? k1 : -1);
            if (k >= 0) w1 = src[k * N + n];
        }
        int di = ((kt * TN_dst + nt_off + ntl) * 32 + lane) * 2 + r;
        dst[di] = pack_f16(w0, w1);
    }
}

__device__ __forceinline__ void cp_smem(float* dst, const float* __restrict__ src, int n) {
    for (int i = threadIdx.x; i < n; i += THREADS) dst[i] = src[i];
}

__global__ void __launch_bounds__(THREADS, 1) robustsym_mma_kernel(
    const float* __restrict__ x,
    const float* __restrict__ gWsym, const float* __restrict__ gbsym,
    const float* __restrict__ gWin,  const float* __restrict__ gbin,
    const float* __restrict__ gW1,   const float* __restrict__ gb1,
    const float* __restrict__ gW2,   const float* __restrict__ gb2,
    const float* __restrict__ gW3,   const float* __restrict__ gb3,
    const float* __restrict__ gWr1,  const float* __restrict__ gbr1,
    const float* __restrict__ gWr2,  const float* __restrict__ gbr2,
    const float* __restrict__ gWc1,  const float* __restrict__ gbc1,
    const float* __restrict__ gWc2,  const float* __restrict__ gbc2,
    float* __restrict__ out, int B)
{
    extern __shared__ float S[];
    unsigned* U = reinterpret_cast<unsigned*>(S);

    // ---- one-time weight convert+permute and bias staging ----
    stage_w(U + OFF_WSYM, gWsym, 10, 32, 1, 4, 4, 0, 0);
    stage_w(U + OFF_WIN,  gWin,  42, 64, 3, 8, 8, 0, 1);
    stage_w(U + OFF_W1,        gW1, 64, 64, 4, 8, 8, 0, 0);
    stage_w(U + OFF_W1 + 4096, gW2, 64, 64, 4, 8, 8, 0, 0);
    stage_w(U + OFF_W1 + 8192, gW3, 64, 64, 4, 8, 8, 0, 0);
    stage_w(U + OFF_WHD, gWr1, 64, 32, 4, 8, 4, 0, 0);
    stage_w(U + OFF_WHD, gWc1, 64, 32, 4, 8, 4, 4, 0);
    cp_smem(S + OFF_BSYM, gbsym, 32);
    cp_smem(S + OFF_BIN,  gbin,  64);
    cp_smem(S + OFF_B1,       gb1, 64);
    cp_smem(S + OFF_B1 + 64,  gb2, 64);
    cp_smem(S + OFF_B1 + 128, gb3, 64);
    cp_smem(S + OFF_BR1, gbr1, 32);
    cp_smem(S + OFF_WR2, gWr2, 32);
    cp_smem(S + OFF_BC1, gbc1, 32);
    cp_smem(S + OFF_WC2, gWc2, 128);
    cp_smem(S + OFF_BC2, gbc2, 4);
    if (threadIdx.x == 0) S[OFF_BR2] = gbr2[0];
    __syncthreads();

    const int wid  = threadIdx.x >> 5;
    const int lane = threadIdx.x & 31;
    const int q = lane & 3, g = lane >> 2;
    unsigned* Uw = U + OFF_STAGE + wid * STAGE_U32_PER_WARP;

    const int ntiles = (B + TILE_ROWS - 1) / TILE_ROWS;
    const int gw = blockIdx.x * WARPS + wid;

    for (int tile = gw; tile < ntiles; tile += GRID * WARPS) {
        const int row0 = tile * TILE_ROWS;

        // ---- phase 0: per-lane features, packed f16x2 into staging ----
        {
            int row = row0 + lane;
            int rq = row < B ? row : B - 1;
            float xr[10];
            #pragma unroll
            for (int i = 0; i < 10; i++) xr[i] = __ldg(x + (long long)rq * 10 + i);

            const float am = xr[0], bod = xr[1], dox = xr[2], ph = xr[4], nit = xr[7];
            float p_ph  = ph  < 6.5f   ? (6.5f   - ph ) * (1.0f/6.5f)  : (ph  > 8.5f ? (ph  - 8.5f) * (1.0f/8.5f) : 0.0f);
            float p_am  = am  < 0.001f ? (0.001f - am ) * 1000.0f      : (am  > 0.5f ? (am  - 0.5f) * 2.0f        : 0.0f);
            float p_bod = bod < 0.001f ? (0.001f - bod) * 1000.0f      : (bod > 5.0f ? (bod - 5.0f) * 0.2f        : 0.0f);
            float p_do  = dox < 6.0f   ? (6.0f   - dox) * (1.0f/6.0f)  : 0.0f;
            float p_nit = nit < 0.001f ? (0.001f - nit) * 1000.0f      : (nit > 10.0f ? (nit - 10.0f) * 0.1f      : 0.0f);
            float s_bact = am * 0.79999998f + bod * 0.099999998f - dox * 0.026666667f;
            float s_chem = ph * 0.088235293f + nit * 0.050000000f;
            float s_org  = bod * 0.13333333f - dox * 0.050000000f + am * 0.53333332f;
            float s_agr  = nit * 0.19999999980000002f;
            float psum   = p_ph + p_am + p_bod + p_do + p_nit;
            float resil  = 1.0f / (1.0f + psum + 1e-8f);

            unsigned* sw = Uw + lane * SSR;
            sw[0]  = pack_f16(p_ph, p_am);
            sw[1]  = pack_f16(p_bod, p_do);
            sw[2]  = pack_f16(p_nit, s_bact);
            sw[3]  = pack_f16(s_chem, s_org);
            sw[4]  = pack_f16(s_agr, resil);
            sw[5] = 0u; sw[6] = 0u; sw[7] = 0u;
            sw[8]  = pack_f16(xr[0], xr[1]);
            sw[9]  = pack_f16(xr[2], xr[3]);
            sw[10] = pack_f16(xr[4], xr[5]);
            sw[11] = pack_f16(xr[6], xr[7]);
            sw[12] = pack_f16(xr[8], xr[9]);
            sw[13] = 0u; sw[14] = 0u; sw[15] = 0u;
        }
        __syncwarp();

        // ---- two independent 16-row halves ----
        #pragma unroll 1
        for (int mt = 0; mt < 2; mt++) {
            const int r0 = mt * 16 + g, r1 = r0 + 8;

            // ---- GEMM A: sym_enc = elu(sym @ W_sym + b_sym)  [16 x 16 -> 32] ----
            float Ca[4][4];
            #pragma unroll
            for (int nt = 0; nt < 4; nt++)
                initC(Ca[nt], *reinterpret_cast<const float2*>(S + OFF_BSYM + nt * 8 + 2 * q));
            {
                unsigned a[4];
                a[0] = Uw[r0 * SSR + q];     a[1] = Uw[r1 * SSR + q];
                a[2] = Uw[r0 * SSR + 4 + q]; a[3] = Uw[r1 * SSR + 4 + q];
                #pragma unroll
                for (int nt = 0; nt < 4; nt++)
                    mma1(Ca[nt], a, U + OFF_WSYM, (nt * 32 + lane) * 2);
            }
            // sym_enc -> packed half2 A-frags for GEMM B kt=0,1 (ELU in half2)
            unsigned aA[2][4];
            #pragma unroll
            for (int kt = 0; kt < 2; kt++) {
                aA[kt][0] = elu_h2(pack_f16(Ca[2*kt][0],   Ca[2*kt][1]));
                aA[kt][1] = elu_h2(pack_f16(Ca[2*kt][2],   Ca[2*kt][3]));
                aA[kt][2] = elu_h2(pack_f16(Ca[2*kt+1][0], Ca[2*kt+1][1]));
                aA[kt][3] = elu_h2(pack_f16(Ca[2*kt+1][2], Ca[2*kt+1][3]));
            }

            // ---- GEMM B: h = elu([sym_enc|x] @ Win_perm + b_in)  [16 x 48 -> 64] ----
            float Cb[8][4];
            #pragma unroll
            for (int nt = 0; nt < 8; nt++)
                initC(Cb[nt], *reinterpret_cast<const float2*>(S + OFF_BIN + nt * 8 + 2 * q));
            #pragma unroll
            for (int kt = 0; kt < 2; kt++)
                #pragma unroll
                for (int nt = 0; nt < 8; nt++)
                    mma1(Cb[nt], aA[kt], U + OFF_WIN, ((kt * 8 + nt) * 32 + lane) * 2);
            {
                unsigned a[4];
                a[0] = Uw[r0 * SSR + 8 + q];  a[1] = Uw[r1 * SSR + 8 + q];
                a[2] = Uw[r0 * SSR + 12 + q]; a[3] = Uw[r1 * SSR + 12 + q];
                #pragma unroll
                for (int nt = 0; nt < 8; nt++)
                    mma1(Cb[nt], a, U + OFF_WIN, ((2 * 8 + nt) * 32 + lane) * 2);
            }
            // h state in packed half2: h2[nt][0] = rows g pair, h2[nt][1] = rows g+8 pair
            unsigned h2[8][2];
            #pragma unroll
            for (int nt = 0; nt < 8; nt++) {
                h2[nt][0] = elu_h2(pack_f16(Cb[nt][0], Cb[nt][1]));
                h2[nt][1] = elu_h2(pack_f16(Cb[nt][2], Cb[nt][3]));
            }

            // ---- residual blocks: h = h + elu(h @ W + b)  x3, half2 state, zero repack ----
            #pragma unroll 1
            for (int l = 0; l < 3; l++) {
                const unsigned* W = U + OFF_W1 + l * 4096;
                const float* bb = S + OFF_B1 + l * 64;
                float C[8][4];
                #pragma unroll
                for (int nt = 0; nt < 8; nt++)
                    initC(C[nt], *reinterpret_cast<const float2*>(bb + nt * 8 + 2 * q));
                #pragma unroll
                for (int kt = 0; kt < 4; kt++) {
                    unsigned a[4] = {h2[2*kt][0], h2[2*kt][1], h2[2*kt+1][0], h2[2*kt+1][1]};
                    #pragma unroll
                    for (int nt = 0; nt < 8; nt++)
                        mma1(C[nt], a, W, ((kt * 8 + nt) * 32 + lane) * 2);
                }
                #pragma unroll
                for (int nt = 0; nt < 8; nt++) {
                    unsigned e0 = elu_h2(pack_f16(C[nt][0], C[nt][1]));
                    unsigned e1 = elu_h2(pack_f16(C[nt][2], C[nt][3]));
                    __half2 v0 = __hadd2(*reinterpret_cast<__half2*>(&h2[nt][0]),
                                         *reinterpret_cast<__half2*>(&e0));
                    __half2 v1 = __hadd2(*reinterpret_cast<__half2*>(&h2[nt][1]),
                                         *reinterpret_cast<__half2*>(&e1));
                    h2[nt][0] = *reinterpret_cast<unsigned*>(&v0);
                    h2[nt][1] = *reinterpret_cast<unsigned*>(&v1);
                }
            }

            // ---- heads (combined TN=8: nt0..3 = Wr1+br1, nt4..7 = Wc1+bc1), f32 epilogue ----
            float C[8][4];
            #pragma unroll
            for (int nt = 0; nt < 4; nt++)
                initC(C[nt], *reinterpret_cast<const float2*>(S + OFF_BR1 + nt * 8 + 2 * q));
            #pragma unroll
            for (int nt = 0; nt < 4; nt++)
                initC(C[4 + nt], *reinterpret_cast<const float2*>(S + OFF_BC1 + nt * 8 + 2 * q));
            #pragma unroll
            for (int kt = 0; kt < 4; kt++) {
                unsigned a[4] = {h2[2*kt][0], h2[2*kt][1], h2[2*kt+1][0], h2[2*kt+1][1]};
                #pragma unroll
                for (int nt = 0; nt < 8; nt++)
                    mma1(C[nt], a, U + OFF_WHD, ((kt * 8 + nt) * 32 + lane) * 2);
            }

            // regression: pred = elu(C[0..3]) @ Wr2 + br2
            {
                const float br2v = S[OFF_BR2];
                float s0 = 0.0f, s1 = 0.0f;
                #pragma unroll
                for (int nt = 0; nt < 4; nt++) {
                    int col = nt * 8 + 2 * q;
                    float2 w = *reinterpret_cast<const float2*>(S + OFF_WR2 + col);
                    s0 += elu_f(C[nt][0]) * w.x + elu_f(C[nt][1]) * w.y;
                    s1 += elu_f(C[nt][2]) * w.x + elu_f(C[nt][3]) * w.y;
                }
                s0 += __shfl_xor_sync(0xFFFFFFFFu, s0, 1);
                s0 += __shfl_xor_sync(0xFFFFFFFFu, s0, 2);
                s1 += __shfl_xor_sync(0xFFFFFFFFu, s1, 1);
                s1 += __shfl_xor_sync(0xFFFFFFFFu, s1, 2);
                if (q == 0) {
                    int r = row0 + mt * 16 + g;
                    if (r < B)     out[r]     = s0 + br2v;
                    if (r + 8 < B) out[r + 8] = s1 + br2v;
                }
            }

            // classification: logits = elu(C[4..7]) @ Wc2 + bc2
            {
                float4 bc2v = *reinterpret_cast<const float4*>(S + OFF_BC2);
                float4 v0 = make_float4(0.f, 0.f, 0.f, 0.f);
                float4 v1 = make_float4(0.f, 0.f, 0.f, 0.f);
                #pragma unroll
                for (int ntl = 0; ntl < 4; ntl++) {
                    const float* Cc = C[4 + ntl];
                    int col = ntl * 8 + 2 * q;
                    float e0 = elu_f(Cc[0]), e1 = elu_f(Cc[1]);
                    float e2 = elu_f(Cc[2]), e3 = elu_f(Cc[3]);
                    float4 w0 = *reinterpret_cast<const float4*>(S + OFF_WC2 + col * 4);
                    float4 w1 = *reinterpret_cast<const float4*>(S + OFF_WC2 + (col + 1) * 4);
                    v0.x += e0 * w0.x + e1 * w1.x; v0.y += e0 * w0.y + e1 * w1.y;
                    v0.z += e0 * w0.z + e1 * w1.z; v0.w += e0 * w0.w + e1 * w1.w;
                    v1.x += e2 * w0.x + e3 * w1.x; v1.y += e2 * w0.y + e3 * w1.y;
                    v1.z += e2 * w0.z + e3 * w1.z; v1.w += e2 * w0.w + e3 * w1.w;
                }
                #pragma unroll
                for (int d = 1; d <= 2; d <<= 1) {
                    v0.x += __shfl_xor_sync(0xFFFFFFFFu, v0.x, d);
                    v0.y += __shfl_xor_sync(0xFFFFFFFFu, v0.y, d);
                    v0.z += __shfl_xor_sync(0xFFFFFFFFu, v0.z, d);
                    v0.w += __shfl_xor_sync(0xFFFFFFFFu, v0.w, d);
                    v1.x += __shfl_xor_sync(0xFFFFFFFFu, v1.x, d);
                    v1.y += __shfl_xor_sync(0xFFFFFFFFu, v1.y, d);
                    v1.z += __shfl_xor_sync(0xFFFFFFFFu, v1.z, d);
                    v1.w += __shfl_xor_sync(0xFFFFFFFFu, v1.w, d);
                }
                if (q == 0) {
                    int r = row0 + mt * 16 + g;
                    if (r < B) {
                        float4 o = make_float4(v0.x + bc2v.x, v0.y + bc2v.y,
                                               v0.z + bc2v.z, v0.w + bc2v.w);
                        *reinterpret_cast<float4*>(out + B + 4LL * r) = o;
                    }
                    if (r + 8 < B) {
                        float4 o = make_float4(v1.x + bc2v.x, v1.y + bc2v.y,
                                               v1.z + bc2v.z, v1.w + bc2v.w);
                        *reinterpret_cast<float4*>(out + B + 4LL * (r + 8)) = o;
                    }
                }
            }
        }
        __syncwarp();
    }
}

extern "C" void kernel_launch(void* const* d_in, const int* in_sizes, int n_in,
                              void* d_out, int out_size) {
    const float* x    = (const float*)d_in[0];
    const float* Wsym = (const float*)d_in[1];
    const float* bsym = (const float*)d_in[2];
    const float* Win  = (const float*)d_in[3];
    const float* bin_ = (const float*)d_in[4];
    const float* W1   = (const float*)d_in[5];
    const float* b1   = (const float*)d_in[6];
    const float* W2   = (const float*)d_in[7];
    const float* b2   = (const float*)d_in[8];
    const float* W3   = (const float*)d_in[9];
    const float* b3   = (const float*)d_in[10];
    const float* Wr1  = (const float*)d_in[11];
    const float* br1  = (const float*)d_in[12];
    const float* Wr2  = (const float*)d_in[13];
    const float* br2  = (const float*)d_in[14];
    const float* Wc1  = (const float*)d_in[15];
    const float* bc1  = (const float*)d_in[16];
    const float* Wc2  = (const float*)d_in[17];
    const float* bc2  = (const float*)d_in[18];
    float* out = (float*)d_out;

    int B = in_sizes[0] / 10;

    cudaFuncSetAttribute(robustsym_mma_kernel,
                         cudaFuncAttributeMaxDynamicSharedMemorySize, SMEM_BYTES);

    robustsym_mma_kernel<<<GRID, THREADS, SMEM_BYTES>>>(
        x, Wsym, bsym, Win, bin_, W1, b1, W2, b2, W3, b3,
        Wr1, br1, Wr2, br2, Wc1, bc1, Wc2, bc2, out, B);
}

// round 14
// speedup vs baseline: 1.1839x; 1.1839x over previous
#include <cuda_runtime.h>
#include <cuda_fp16.h>

#define THREADS 512
#define WARPS 16
#define GRID 148
#define TILE_ROWS 32
#define SSR 36              // staging row stride in u32: bank(36g+q)=4g+q -> conflict-free frag reads

// ---- smem layout ----
// Weight region (u32 units): entry ((kt*TN+nt)*32+lane)*2+r packs f16x2 (RN fp16 of w)
// for the B-frag of mma.m16n8k16.
#define OFF_WSYM 0            // TK=1 TN=4 : 256
#define OFF_WIN  512          // TK=3 TN=8 : 1536  (rows permuted: [sym32|x10|pad6])
#define OFF_W1   3584         // TK=4 TN=8 : 2048 each, stride 4096 (x3)
#define OFF_WHD  15872        // heads combined Wr1(nt0..3)+Wc1(nt4..7): TK=4 TN=8 : 2048
// bias region (float units)
#define OFF_BSYM 19968
#define OFF_BIN  20000
#define OFF_B1   20064        // 64*3
#define OFF_BR1  20256
#define OFF_WR2  20288
#define OFF_BC1  20320
#define OFF_WC2  20352        // 32x4
#define OFF_BC2  20480
#define OFF_BR2  20484
#define OFF_STAGE 20488       // u32/float offset; per-warp 32 rows * 36 u32
#define STAGE_U32_PER_WARP (TILE_ROWS * SSR)   // 1152
#define SMEM_FLOATS (OFF_STAGE + WARPS * STAGE_U32_PER_WARP)
#define SMEM_BYTES (SMEM_FLOATS * 4)

// branchless ELU
__device__ __forceinline__ float elu_f(float v) {
    float e = __expf(v) - 1.0f;
    return v > 0.0f ? v : e;
}

__device__ __forceinline__ void mma_f16(float* c, const unsigned* a, unsigned b0, unsigned b1) {
    asm volatile(
        "mma.sync.aligned.m16n8k16.row.col.f32.f16.f16.f32 "
        "{%0,%1,%2,%3},{%4,%5,%6,%7},{%8,%9},{%0,%1,%2,%3};\n"
        : "+f"(c[0]), "+f"(c[1]), "+f"(c[2]), "+f"(c[3])
        : "r"(a[0]), "r"(a[1]), "r"(a[2]), "r"(a[3]), "r"(b0), "r"(b1));
}

// Pack two floats into f16x2 (RN). Low half = x (first k).
__device__ __forceinline__ unsigned pack_f16(float x, float y) {
    unsigned r;
    asm("cvt.rn.f16x2.f32 %0, %1, %2;" : "=r"(r) : "f"(y), "f"(x));
    return r;
}

// 1-term MMA step: C += A * B (single RN-fp16 weight term)
__device__ __forceinline__ void mma1(float* c, const unsigned* a,
                                     const unsigned* W, int idx) {
    uint2 b = *(const uint2*)(W + idx);
    mma_f16(c, a, b.x, b.y);
}

// Init accumulator quad with bias pair (b.x->cols 2q, b.y->cols 2q+1, both row groups).
__device__ __forceinline__ void initC(float* c, float2 b) {
    c[0] = b.x; c[1] = b.y; c[2] = b.x; c[3] = b.y;
}

// Pack A-fragment (one kt, one mt) from two ELU'd C tiles (C layout == A layout).
// m16n8k16 A order: a0 = C[2kt] rows g; a1 = C[2kt] rows g+8;
//                   a2 = C[2kt+1] rows g; a3 = C[2kt+1] rows g+8.
__device__ __forceinline__ void pack2(const float* c0, const float* c1, unsigned* a) {
    a[0] = pack_f16(c0[0], c0[1]);
    a[1] = pack_f16(c0[2], c0[3]);
    a[2] = pack_f16(c1[0], c1[1]);
    a[3] = pack_f16(c1[2], c1[3]);
}

// Stage W[K,N] row-major -> permuted packed-f16 B-frag layout (RN fp16), zero-padded.
// perm=1: W_in row remap (dst feature order [sym_enc(32)|x(10)|pad(6)]).
__device__ void stage_w(unsigned* dst, const float* __restrict__ src,
                        int K, int N, int TK, int TN_dst, int srcT, int nt_off, int perm) {
    int total = TK * srcT * 64;
    for (int i = threadIdx.x; i < total; i += THREADS) {
        int r = i & 1, lane = (i >> 1) & 31, t = i >> 6;
        int kt = t / srcT, ntl = t % srcT;
        int q = lane & 3, g = lane >> 2;
        int k0 = kt * 16 + r * 8 + 2 * q;
        int n = ntl * 8 + g;
        float w0 = 0.0f, w1 = 0.0f;
        if (n < N) {
            int k = perm ? ((k0 < 32) ? k0 + 10 : (k0 < 42 ? k0 - 32 : -1))
                         : (k0 < K ? k0 : -1);
            if (k >= 0) w0 = src[k * N + n];
            int k1 = k0 + 1;
            k = perm ? ((k1 < 32) ? k1 + 10 : (k1 < 42 ? k1 - 32 : -1))
                     : (k1 < K ? k1 : -1);
            if (k >= 0) w1 = src[k * N + n];
        }
        int di = ((kt * TN_dst + nt_off + ntl) * 32 + lane) * 2 + r;
        dst[di] = pack_f16(w0, w1);
    }
}

__device__ __forceinline__ void cp_smem(float* dst, const float* __restrict__ src, int n) {
    for (int i = threadIdx.x; i < n; i += THREADS) dst[i] = src[i];
}

__global__ void __launch_bounds__(THREADS, 1) robustsym_mma_kernel(
    const float* __restrict__ x,
    const float* __restrict__ gWsym, const float* __restrict__ gbsym,
    const float* __restrict__ gWin,  const float* __restrict__ gbin,
    const float* __restrict__ gW1,   const float* __restrict__ gb1,
    const float* __restrict__ gW2,   const float* __restrict__ gb2,
    const float* __restrict__ gW3,   const float* __restrict__ gb3,
    const float* __restrict__ gWr1,  const float* __restrict__ gbr1,
    const float* __restrict__ gWr2,  const float* __restrict__ gbr2,
    const float* __restrict__ gWc1,  const float* __restrict__ gbc1,
    const float* __restrict__ gWc2,  const float* __restrict__ gbc2,
    float* __restrict__ out, int B)
{
    extern __shared__ float S[];
    unsigned* U = reinterpret_cast<unsigned*>(S);

    // ---- one-time weight convert+permute and bias staging ----
    stage_w(U + OFF_WSYM, gWsym, 10, 32, 1, 4, 4, 0, 0);
    stage_w(U + OFF_WIN,  gWin,  42, 64, 3, 8, 8, 0, 1);
    stage_w(U + OFF_W1,        gW1, 64, 64, 4, 8, 8, 0, 0);
    stage_w(U + OFF_W1 + 4096, gW2, 64, 64, 4, 8, 8, 0, 0);
    stage_w(U + OFF_W1 + 8192, gW3, 64, 64, 4, 8, 8, 0, 0);
    stage_w(U + OFF_WHD, gWr1, 64, 32, 4, 8, 4, 0, 0);
    stage_w(U + OFF_WHD, gWc1, 64, 32, 4, 8, 4, 4, 0);
    cp_smem(S + OFF_BSYM, gbsym, 32);
    cp_smem(S + OFF_BIN,  gbin,  64);
    cp_smem(S + OFF_B1,       gb1, 64);
    cp_smem(S + OFF_B1 + 64,  gb2, 64);
    cp_smem(S + OFF_B1 + 128, gb3, 64);
    cp_smem(S + OFF_BR1, gbr1, 32);
    cp_smem(S + OFF_WR2, gWr2, 32);
    cp_smem(S + OFF_BC1, gbc1, 32);
    cp_smem(S + OFF_WC2, gWc2, 128);
    cp_smem(S + OFF_BC2, gbc2, 4);
    if (threadIdx.x == 0) S[OFF_BR2] = gbr2[0];
    __syncthreads();

    const int wid  = threadIdx.x >> 5;
    const int lane = threadIdx.x & 31;
    const int q = lane & 3, g = lane >> 2;
    unsigned* Uw = U + OFF_STAGE + wid * STAGE_U32_PER_WARP;

    const int ntiles = (B + TILE_ROWS - 1) / TILE_ROWS;
    const int gw = blockIdx.x * WARPS + wid;

    for (int tile = gw; tile < ntiles; tile += GRID * WARPS) {
        const int row0 = tile * TILE_ROWS;

        // ---- phase 0: per-lane features, packed f16x2 into staging ----
        {
            int row = row0 + lane;
            int rq = row < B ? row : B - 1;
            float xr[10];
            #pragma unroll
            for (int i = 0; i < 10; i++) xr[i] = __ldg(x + (long long)rq * 10 + i);

            const float am = xr[0], bod = xr[1], dox = xr[2], ph = xr[4], nit = xr[7];
            float p_ph  = ph  < 6.5f   ? (6.5f   - ph ) * (1.0f/6.5f)  : (ph  > 8.5f ? (ph  - 8.5f) * (1.0f/8.5f) : 0.0f);
            float p_am  = am  < 0.001f ? (0.001f - am ) * 1000.0f      : (am  > 0.5f ? (am  - 0.5f) * 2.0f        : 0.0f);
            float p_bod = bod < 0.001f ? (0.001f - bod) * 1000.0f      : (bod > 5.0f ? (bod - 5.0f) * 0.2f        : 0.0f);
            float p_do  = dox < 6.0f   ? (6.0f   - dox) * (1.0f/6.0f)  : 0.0f;
            float p_nit = nit < 0.001f ? (0.001f - nit) * 1000.0f      : (nit > 10.0f ? (nit - 10.0f) * 0.1f      : 0.0f);
            float s_bact = am * 0.79999998f + bod * 0.099999998f - dox * 0.026666667f;
            float s_chem = ph * 0.088235293f + nit * 0.050000000f;
            float s_org  = bod * 0.13333333f - dox * 0.050000000f + am * 0.53333332f;
            float s_agr  = nit * 0.19999999980000002f;
            float psum   = p_ph + p_am + p_bod + p_do + p_nit;
            float resil  = 1.0f / (1.0f + psum + 1e-8f);

            unsigned* sw = Uw + lane * SSR;
            sw[0]  = pack_f16(p_ph, p_am);
            sw[1]  = pack_f16(p_bod, p_do);
            sw[2]  = pack_f16(p_nit, s_bact);
            sw[3]  = pack_f16(s_chem, s_org);
            sw[4]  = pack_f16(s_agr, resil);
            sw[5] = 0u; sw[6] = 0u; sw[7] = 0u;
            sw[8]  = pack_f16(xr[0], xr[1]);
            sw[9]  = pack_f16(xr[2], xr[3]);
            sw[10] = pack_f16(xr[4], xr[5]);
            sw[11] = pack_f16(xr[6], xr[7]);
            sw[12] = pack_f16(xr[8], xr[9]);
            sw[13] = 0u; sw[14] = 0u; sw[15] = 0u;
        }
        __syncwarp();

        // ---- two independent 16-row halves ----
        #pragma unroll 1
        for (int mt = 0; mt < 2; mt++) {
            const int r0 = mt * 16 + g, r1 = r0 + 8;

            // ---- GEMM A: sym_enc = elu(sym @ W_sym + b_sym)  [16 x 16 -> 32] ----
            float Ca[4][4];
            #pragma unroll
            for (int nt = 0; nt < 4; nt++)
                initC(Ca[nt], *reinterpret_cast<const float2*>(S + OFF_BSYM + nt * 8 + 2 * q));
            {
                unsigned a[4];
                a[0] = Uw[r0 * SSR + q];     a[1] = Uw[r1 * SSR + q];
                a[2] = Uw[r0 * SSR + 4 + q]; a[3] = Uw[r1 * SSR + 4 + q];
                #pragma unroll
                for (int nt = 0; nt < 4; nt++)
                    mma1(Ca[nt], a, U + OFF_WSYM, (nt * 32 + lane) * 2);
            }
            #pragma unroll
            for (int nt = 0; nt < 4; nt++) {
                Ca[nt][0] = elu_f(Ca[nt][0]); Ca[nt][1] = elu_f(Ca[nt][1]);
                Ca[nt][2] = elu_f(Ca[nt][2]); Ca[nt][3] = elu_f(Ca[nt][3]);
            }

            // pack sym_enc into A-frags for GEMM B kt=0,1 (register-to-register)
            unsigned aA[2][4];
            pack2(Ca[0], Ca[1], aA[0]);
            pack2(Ca[2], Ca[3], aA[1]);

            // ---- GEMM B: h = elu([sym_enc|x] @ Win_perm + b_in)  [16 x 48 -> 64] ----
            float h[8][4];
            #pragma unroll
            for (int nt = 0; nt < 8; nt++)
                initC(h[nt], *reinterpret_cast<const float2*>(S + OFF_BIN + nt * 8 + 2 * q));
            #pragma unroll
            for (int kt = 0; kt < 2; kt++)
                #pragma unroll
                for (int nt = 0; nt < 8; nt++)
                    mma1(h[nt], aA[kt], U + OFF_WIN, ((kt * 8 + nt) * 32 + lane) * 2);
            {
                unsigned a[4];
                a[0] = Uw[r0 * SSR + 8 + q];  a[1] = Uw[r1 * SSR + 8 + q];
                a[2] = Uw[r0 * SSR + 12 + q]; a[3] = Uw[r1 * SSR + 12 + q];
                #pragma unroll
                for (int nt = 0; nt < 8; nt++)
                    mma1(h[nt], a, U + OFF_WIN, ((2 * 8 + nt) * 32 + lane) * 2);
            }
            #pragma unroll
            for (int nt = 0; nt < 8; nt++) {
                h[nt][0] = elu_f(h[nt][0]); h[nt][1] = elu_f(h[nt][1]);
                h[nt][2] = elu_f(h[nt][2]); h[nt][3] = elu_f(h[nt][3]);
            }

            // ---- residual blocks: h = h + elu(h @ W + b)  x3, fully in registers ----
            #pragma unroll 1
            for (int l = 0; l < 3; l++) {
                const unsigned* W = U + OFF_W1 + l * 4096;
                const float* bb = S + OFF_B1 + l * 64;
                float C[8][4];
                #pragma unroll
                for (int nt = 0; nt < 8; nt++)
                    initC(C[nt], *reinterpret_cast<const float2*>(bb + nt * 8 + 2 * q));
                #pragma unroll
                for (int kt = 0; kt < 4; kt++) {
                    unsigned a[4];
                    pack2(h[2 * kt], h[2 * kt + 1], a);
                    #pragma unroll
                    for (int nt = 0; nt < 8; nt++)
                        mma1(C[nt], a, W, ((kt * 8 + nt) * 32 + lane) * 2);
                }
                #pragma unroll
                for (int nt = 0; nt < 8; nt++) {
                    h[nt][0] += elu_f(C[nt][0]); h[nt][1] += elu_f(C[nt][1]);
                    h[nt][2] += elu_f(C[nt][2]); h[nt][3] += elu_f(C[nt][3]);
                }
            }

            // ---- heads (combined TN=8: nt0..3 = Wr1+br1, nt4..7 = Wc1+bc1) ----
            float C[8][4];
            #pragma unroll
            for (int nt = 0; nt < 4; nt++)
                initC(C[nt], *reinterpret_cast<const float2*>(S + OFF_BR1 + nt * 8 + 2 * q));
            #pragma unroll
            for (int nt = 0; nt < 4; nt++)
                initC(C[4 + nt], *reinterpret_cast<const float2*>(S + OFF_BC1 + nt * 8 + 2 * q));
            #pragma unroll
            for (int kt = 0; kt < 4; kt++) {
                unsigned a[4];
                pack2(h[2 * kt], h[2 * kt + 1], a);
                #pragma unroll
                for (int nt = 0; nt < 8; nt++)
                    mma1(C[nt], a, U + OFF_WHD, ((kt * 8 + nt) * 32 + lane) * 2);
            }

            // regression: pred = elu(C[0..3]) @ Wr2 + br2
            {
                const float br2v = S[OFF_BR2];
                float s0 = 0.0f, s1 = 0.0f;
                #pragma unroll
                for (int nt = 0; nt < 4; nt++) {
                    int col = nt * 8 + 2 * q;
                    float2 w = *reinterpret_cast<const float2*>(S + OFF_WR2 + col);
                    s0 += elu_f(C[nt][0]) * w.x + elu_f(C[nt][1]) * w.y;
                    s1 += elu_f(C[nt][2]) * w.x + elu_f(C[nt][3]) * w.y;
                }
                s0 += __shfl_xor_sync(0xFFFFFFFFu, s0, 1);
                s0 += __shfl_xor_sync(0xFFFFFFFFu, s0, 2);
                s1 += __shfl_xor_sync(0xFFFFFFFFu, s1, 1);
                s1 += __shfl_xor_sync(0xFFFFFFFFu, s1, 2);
                if (q == 0) {
                    int r = row0 + mt * 16 + g;
                    if (r < B)     out[r]     = s0 + br2v;
                    if (r + 8 < B) out[r + 8] = s1 + br2v;
                }
            }

            // classification: logits = elu(C[4..7]) @ Wc2 + bc2
            {
                float4 bc2v = *reinterpret_cast<const float4*>(S + OFF_BC2);
                float4 v0 = make_float4(0.f, 0.f, 0.f, 0.f);
                float4 v1 = make_float4(0.f, 0.f, 0.f, 0.f);
                #pragma unroll
                for (int ntl = 0; ntl < 4; ntl++) {
                    const float* Cc = C[4 + ntl];
                    int col = ntl * 8 + 2 * q;
                    float e0 = elu_f(Cc[0]), e1 = elu_f(Cc[1]);
                    float e2 = elu_f(Cc[2]), e3 = elu_f(Cc[3]);
                    float4 w0 = *reinterpret_cast<const float4*>(S + OFF_WC2 + col * 4);
                    float4 w1 = *reinterpret_cast<const float4*>(S + OFF_WC2 + (col + 1) * 4);
                    v0.x += e0 * w0.x + e1 * w1.x; v0.y += e0 * w0.y + e1 * w1.y;
                    v0.z += e0 * w0.z + e1 * w1.z; v0.w += e0 * w0.w + e1 * w1.w;
                    v1.x += e2 * w0.x + e3 * w1.x; v1.y += e2 * w0.y + e3 * w1.y;
                    v1.z += e2 * w0.z + e3 * w1.z; v1.w += e2 * w0.w + e3 * w1.w;
                }
                #pragma unroll
                for (int d = 1; d <= 2; d <<= 1) {
                    v0.x += __shfl_xor_sync(0xFFFFFFFFu, v0.x, d);
                    v0.y += __shfl_xor_sync(0xFFFFFFFFu, v0.y, d);
                    v0.z += __shfl_xor_sync(0xFFFFFFFFu, v0.z, d);
                    v0.w += __shfl_xor_sync(0xFFFFFFFFu, v0.w, d);
                    v1.x += __shfl_xor_sync(0xFFFFFFFFu, v1.x, d);
                    v1.y += __shfl_xor_sync(0xFFFFFFFFu, v1.y, d);
                    v1.z += __shfl_xor_sync(0xFFFFFFFFu, v1.z, d);
                    v1.w += __shfl_xor_sync(0xFFFFFFFFu, v1.w, d);
                }
                if (q == 0) {
                    int r = row0 + mt * 16 + g;
                    if (r < B) {
                        float4 o = make_float4(v0.x + bc2v.x, v0.y + bc2v.y,
                                               v0.z + bc2v.z, v0.w + bc2v.w);
                        *reinterpret_cast<float4*>(out + B + 4LL * r) = o;
                    }
                    if (r + 8 < B) {
                        float4 o = make_float4(v1.x + bc2v.x, v1.y + bc2v.y,
                                               v1.z + bc2v.z, v1.w + bc2v.w);
                        *reinterpret_cast<float4*>(out + B + 4LL * (r + 8)) = o;
                    }
                }
            }
        }
        __syncwarp();
    }
}

extern "C" void kernel_launch(void* const* d_in, const int* in_sizes, int n_in,
                              void* d_out, int out_size) {
    const float* x    = (const float*)d_in[0];
    const float* Wsym = (const float*)d_in[1];
    const float* bsym = (const float*)d_in[2];
    const float* Win  = (const float*)d_in[3];
    const float* bin_ = (const float*)d_in[4];
    const float* W1   = (const float*)d_in[5];
    const float* b1   = (const float*)d_in[6];
    const float* W2   = (const float*)d_in[7];
    const float* b2   = (const float*)d_in[8];
    const float* W3   = (const float*)d_in[9];
    const float* b3   = (const float*)d_in[10];
    const float* Wr1  = (const float*)d_in[11];
    const float* br1  = (const float*)d_in[12];
    const float* Wr2  = (const float*)d_in[13];
    const float* br2  = (const float*)d_in[14];
    const float* Wc1  = (const float*)d_in[15];
    const float* bc1  = (const float*)d_in[16];
    const float* Wc2  = (const float*)d_in[17];
    const float* bc2  = (const float*)d_in[18];
    float* out = (float*)d_out;

    int B = in_sizes[0] / 10;

    cudaFuncSetAttribute(robustsym_mma_kernel,
                         cudaFuncAttributeMaxDynamicSharedMemorySize, SMEM_BYTES);

    robustsym_mma_kernel<<<GRID, THREADS, SMEM_BYTES>>>(
        x, Wsym, bsym, Win, bin_, W1, b1, W2, b2, W3, b3,
        Wr1, br1, Wr2, br2, Wc1, bc1, Wc2, bc2, out, B);
}

// round 16
// speedup vs baseline: 1.2101x; 1.0222x over previous
#include <cuda_runtime.h>
#include <cuda_fp16.h>

#define THREADS 512
#define WARPS 16
#define GRID 148
#define TILE_ROWS 32
#define SSR 36              // staging row stride in u32: bank(36g+q)=4g+q -> conflict-free frag reads

// ---- smem layout ----
// Weight region (u32 units): PAIRED layout. Entry for (kt, nt, lane, r):
//   ((kt*(TN/2) + nt/2)*32 + lane)*4 + (nt&1)*2 + r
// so one LDS.128 yields the B-frags (b0,b1) of nt and nt+1.
#define OFF_WSYM 0            // TK=1 TN=4 : 256
#define OFF_WIN  512          // TK=3 TN=8 : 1536  (rows permuted: [sym32|x10|pad6])
#define OFF_W1   3584         // TK=4 TN=8 : 2048 each, stride 4096 (x3)
#define OFF_WHD  15872        // heads combined Wr1(nt0..3)+Wc1(nt4..7): TK=4 TN=8 : 2048
// bias region (float units)
#define OFF_BSYM 19968
#define OFF_BIN  20000
#define OFF_B1   20064        // 64*3
#define OFF_BR1  20256
#define OFF_WR2  20288
#define OFF_BC1  20320
#define OFF_WC2  20352        // 32x4
#define OFF_BC2  20480
#define OFF_BR2  20484
#define OFF_STAGE 20488       // u32/float offset; per-warp 32 rows * 36 u32
#define STAGE_U32_PER_WARP (TILE_ROWS * SSR)   // 1152
#define SMEM_FLOATS (OFF_STAGE + WARPS * STAGE_U32_PER_WARP)
#define SMEM_BYTES (SMEM_FLOATS * 4)

// branchless ELU (f32 — precision-calibrated at rel_err 2.1e-4)
__device__ __forceinline__ float elu_f(float v) {
    float e = __expf(v) - 1.0f;
    return v > 0.0f ? v : e;
}

__device__ __forceinline__ void mma_f16(float* c, const unsigned* a, unsigned b0, unsigned b1) {
    asm volatile(
        "mma.sync.aligned.m16n8k16.row.col.f32.f16.f16.f32 "
        "{%0,%1,%2,%3},{%4,%5,%6,%7},{%8,%9},{%0,%1,%2,%3};\n"
        : "+f"(c[0]), "+f"(c[1]), "+f"(c[2]), "+f"(c[3])
        : "r"(a[0]), "r"(a[1]), "r"(a[2]), "r"(a[3]), "r"(b0), "r"(b1));
}

// Pack two floats into f16x2 (RN). Low half = x (first element).
__device__ __forceinline__ unsigned pack_f16(float x, float y) {
    unsigned r;
    asm("cvt.rn.f16x2.f32 %0, %1, %2;" : "=r"(r) : "f"(y), "f"(x));
    return r;
}

// Paired MMA step: one LDS.128 feeds two adjacent-nt MMAs.
__device__ __forceinline__ void mma_pair(float* c0, float* c1, const unsigned* a,
                                         const unsigned* W, int idx) {
    uint4 b = *(const uint4*)(W + idx);
    mma_f16(c0, a, b.x, b.y);
    mma_f16(c1, a, b.z, b.w);
}

// Init accumulator quad with bias pair (b.x->cols 2q, b.y->cols 2q+1, both row groups).
__device__ __forceinline__ void initC(float* c, float2 b) {
    c[0] = b.x; c[1] = b.y; c[2] = b.x; c[3] = b.y;
}

// Pack A-fragment (one kt, one mt) from two ELU'd C tiles (C layout == A layout).
// m16n8k16 A order: a0 = C[2kt] rows g; a1 = C[2kt] rows g+8;
//                   a2 = C[2kt+1] rows g; a3 = C[2kt+1] rows g+8.
__device__ __forceinline__ void pack2(const float* c0, const float* c1, unsigned* a) {
    a[0] = pack_f16(c0[0], c0[1]);
    a[1] = pack_f16(c0[2], c0[3]);
    a[2] = pack_f16(c1[0], c1[1]);
    a[3] = pack_f16(c1[2], c1[3]);
}

// Stage W[K,N] row-major -> PAIRED packed-f16 B-frag layout (RN fp16), zero-padded.
// perm=1: W_in row remap (dst feature order [sym_enc(32)|x(10)|pad(6)]).
__device__ void stage_w(unsigned* dst, const float* __restrict__ src,
                        int K, int N, int TK, int TN_dst, int srcT, int nt_off, int perm) {
    int total = TK * srcT * 64;
    int TNh = TN_dst >> 1;
    for (int i = threadIdx.x; i < total; i += THREADS) {
        int r = i & 1, lane = (i >> 1) & 31, t = i >> 6;
        int kt = t / srcT, ntl = t % srcT;
        int q = lane & 3, g = lane >> 2;
        int k0 = kt * 16 + r * 8 + 2 * q;
        int n = ntl * 8 + g;
        float w0 = 0.0f, w1 = 0.0f;
        if (n < N) {
            int k = perm ? ((k0 < 32) ? k0 + 10 : (k0 < 42 ? k0 - 32 : -1))
                         : (k0 < K ? k0 : -1);
            if (k >= 0) w0 = src[k * N + n];
            int k1 = k0 + 1;
            k = perm ? ((k1 < 32) ? k1 + 10 : (k1 < 42 ? k1 - 32 : -1))
                     : (k1 < K ? k1 : -1);
            if (k >= 0) w1 = src[k * N + n];
        }
        int ntg = nt_off + ntl;
        int di = ((kt * TNh + (ntg >> 1)) * 32 + lane) * 4 + (ntg & 1) * 2 + r;
        dst[di] = pack_f16(w0, w1);
    }
}

__device__ __forceinline__ void cp_smem(float* dst, const float* __restrict__ src, int n) {
    for (int i = threadIdx.x; i < n; i += THREADS) dst[i] = src[i];
}

__global__ void __launch_bounds__(THREADS, 1) robustsym_mma_kernel(
    const float* __restrict__ x,
    const float* __restrict__ gWsym, const float* __restrict__ gbsym,
    const float* __restrict__ gWin,  const float* __restrict__ gbin,
    const float* __restrict__ gW1,   const float* __restrict__ gb1,
    const float* __restrict__ gW2,   const float* __restrict__ gb2,
    const float* __restrict__ gW3,   const float* __restrict__ gb3,
    const float* __restrict__ gWr1,  const float* __restrict__ gbr1,
    const float* __restrict__ gWr2,  const float* __restrict__ gbr2,
    const float* __restrict__ gWc1,  const float* __restrict__ gbc1,
    const float* __restrict__ gWc2,  const float* __restrict__ gbc2,
    float* __restrict__ out, int B)
{
    extern __shared__ float S[];
    unsigned* U = reinterpret_cast<unsigned*>(S);

    // ---- one-time weight convert+permute and bias staging ----
    stage_w(U + OFF_WSYM, gWsym, 10, 32, 1, 4, 4, 0, 0);
    stage_w(U + OFF_WIN,  gWin,  42, 64, 3, 8, 8, 0, 1);
    stage_w(U + OFF_W1,        gW1, 64, 64, 4, 8, 8, 0, 0);
    stage_w(U + OFF_W1 + 4096, gW2, 64, 64, 4, 8, 8, 0, 0);
    stage_w(U + OFF_W1 + 8192, gW3, 64, 64, 4, 8, 8, 0, 0);
    stage_w(U + OFF_WHD, gWr1, 64, 32, 4, 8, 4, 0, 0);
    stage_w(U + OFF_WHD, gWc1, 64, 32, 4, 8, 4, 4, 0);
    cp_smem(S + OFF_BSYM, gbsym, 32);
    cp_smem(S + OFF_BIN,  gbin,  64);
    cp_smem(S + OFF_B1,       gb1, 64);
    cp_smem(S + OFF_B1 + 64,  gb2, 64);
    cp_smem(S + OFF_B1 + 128, gb3, 64);
    cp_smem(S + OFF_BR1, gbr1, 32);
    cp_smem(S + OFF_WR2, gWr2, 32);
    cp_smem(S + OFF_BC1, gbc1, 32);
    cp_smem(S + OFF_WC2, gWc2, 128);
    cp_smem(S + OFF_BC2, gbc2, 4);
    if (threadIdx.x == 0) S[OFF_BR2] = gbr2[0];
    __syncthreads();

    const int wid  = threadIdx.x >> 5;
    const int lane = threadIdx.x & 31;
    const int q = lane & 3, g = lane >> 2;
    unsigned* Uw = U + OFF_STAGE + wid * STAGE_U32_PER_WARP;

    const int ntiles = (B + TILE_ROWS - 1) / TILE_ROWS;
    const int gw = blockIdx.x * WARPS + wid;

    for (int tile = gw; tile < ntiles; tile += GRID * WARPS) {
        const int row0 = tile * TILE_ROWS;

        // ---- phase 0: per-lane features, packed f16x2 into staging ----
        {
            int row = row0 + lane;
            int rq = row < B ? row : B - 1;
            float xr[10];
            #pragma unroll
            for (int i = 0; i < 10; i++) xr[i] = __ldg(x + (long long)rq * 10 + i);

            const float am = xr[0], bod = xr[1], dox = xr[2], ph = xr[4], nit = xr[7];
            float p_ph  = ph  < 6.5f   ? (6.5f   - ph ) * (1.0f/6.5f)  : (ph  > 8.5f ? (ph  - 8.5f) * (1.0f/8.5f) : 0.0f);
            float p_am  = am  < 0.001f ? (0.001f - am ) * 1000.0f      : (am  > 0.5f ? (am  - 0.5f) * 2.0f        : 0.0f);
            float p_bod = bod < 0.001f ? (0.001f - bod) * 1000.0f      : (bod > 5.0f ? (bod - 5.0f) * 0.2f        : 0.0f);
            float p_do  = dox < 6.0f   ? (6.0f   - dox) * (1.0f/6.0f)  : 0.0f;
            float p_nit = nit < 0.001f ? (0.001f - nit) * 1000.0f      : (nit > 10.0f ? (nit - 10.0f) * 0.1f      : 0.0f);
            float s_bact = am * 0.79999998f + bod * 0.099999998f - dox * 0.026666667f;
            float s_chem = ph * 0.088235293f + nit * 0.050000000f;
            float s_org  = bod * 0.13333333f - dox * 0.050000000f + am * 0.53333332f;
            float s_agr  = nit * 0.19999999980000002f;
            float psum   = p_ph + p_am + p_bod + p_do + p_nit;
            float resil  = 1.0f / (1.0f + psum + 1e-8f);

            unsigned* sw = Uw + lane * SSR;
            sw[0]  = pack_f16(p_ph, p_am);
            sw[1]  = pack_f16(p_bod, p_do);
            sw[2]  = pack_f16(p_nit, s_bact);
            sw[3]  = pack_f16(s_chem, s_org);
            sw[4]  = pack_f16(s_agr, resil);
            sw[5] = 0u; sw[6] = 0u; sw[7] = 0u;
            sw[8]  = pack_f16(xr[0], xr[1]);
            sw[9]  = pack_f16(xr[2], xr[3]);
            sw[10] = pack_f16(xr[4], xr[5]);
            sw[11] = pack_f16(xr[6], xr[7]);
            sw[12] = pack_f16(xr[8], xr[9]);
            sw[13] = 0u; sw[14] = 0u; sw[15] = 0u;
        }
        __syncwarp();

        // ---- two independent 16-row halves ----
        #pragma unroll 1
        for (int mt = 0; mt < 2; mt++) {
            const int r0 = mt * 16 + g, r1 = r0 + 8;

            // ---- GEMM A: sym_enc = elu(sym @ W_sym + b_sym)  [16 x 16 -> 32] ----
            float Ca[4][4];
            #pragma unroll
            for (int nt = 0; nt < 4; nt++)
                initC(Ca[nt], *reinterpret_cast<const float2*>(S + OFF_BSYM + nt * 8 + 2 * q));
            {
                unsigned a[4];
                a[0] = Uw[r0 * SSR + q];     a[1] = Uw[r1 * SSR + q];
                a[2] = Uw[r0 * SSR + 4 + q]; a[3] = Uw[r1 * SSR + 4 + q];
                #pragma unroll
                for (int p = 0; p < 2; p++)
                    mma_pair(Ca[2*p], Ca[2*p+1], a, U + OFF_WSYM, (p * 32 + lane) * 4);
            }
            #pragma unroll
            for (int nt = 0; nt < 4; nt++) {
                Ca[nt][0] = elu_f(Ca[nt][0]); Ca[nt][1] = elu_f(Ca[nt][1]);
                Ca[nt][2] = elu_f(Ca[nt][2]); Ca[nt][3] = elu_f(Ca[nt][3]);
            }

            // pack sym_enc into A-frags for GEMM B kt=0,1 (register-to-register)
            unsigned aA[2][4];
            pack2(Ca[0], Ca[1], aA[0]);
            pack2(Ca[2], Ca[3], aA[1]);

            // ---- GEMM B: h = elu([sym_enc|x] @ Win_perm + b_in)  [16 x 48 -> 64] ----
            float h[8][4];
            #pragma unroll
            for (int nt = 0; nt < 8; nt++)
                initC(h[nt], *reinterpret_cast<const float2*>(S + OFF_BIN + nt * 8 + 2 * q));
            #pragma unroll
            for (int kt = 0; kt < 2; kt++)
                #pragma unroll
                for (int p = 0; p < 4; p++)
                    mma_pair(h[2*p], h[2*p+1], aA[kt], U + OFF_WIN,
                             ((kt * 4 + p) * 32 + lane) * 4);
            {
                unsigned a[4];
                a[0] = Uw[r0 * SSR + 8 + q];  a[1] = Uw[r1 * SSR + 8 + q];
                a[2] = Uw[r0 * SSR + 12 + q]; a[3] = Uw[r1 * SSR + 12 + q];
                #pragma unroll
                for (int p = 0; p < 4; p++)
                    mma_pair(h[2*p], h[2*p+1], a, U + OFF_WIN,
                             ((2 * 4 + p) * 32 + lane) * 4);
            }
            #pragma unroll
            for (int nt = 0; nt < 8; nt++) {
                h[nt][0] = elu_f(h[nt][0]); h[nt][1] = elu_f(h[nt][1]);
                h[nt][2] = elu_f(h[nt][2]); h[nt][3] = elu_f(h[nt][3]);
            }

            // ---- residual blocks: h = h + elu(h @ W + b)  x3, fully in registers ----
            #pragma unroll 1
            for (int l = 0; l < 3; l++) {
                const unsigned* W = U + OFF_W1 + l * 4096;
                const float* bb = S + OFF_B1 + l * 64;
                float C[8][4];
                #pragma unroll
                for (int nt = 0; nt < 8; nt++)
                    initC(C[nt], *reinterpret_cast<const float2*>(bb + nt * 8 + 2 * q));
                #pragma unroll
                for (int kt = 0; kt < 4; kt++) {
                    unsigned a[4];
                    pack2(h[2 * kt], h[2 * kt + 1], a);
                    #pragma unroll
                    for (int p = 0; p < 4; p++)
                        mma_pair(C[2*p], C[2*p+1], a, W, ((kt * 4 + p) * 32 + lane) * 4);
                }
                #pragma unroll
                for (int nt = 0; nt < 8; nt++) {
                    h[nt][0] += elu_f(C[nt][0]); h[nt][1] += elu_f(C[nt][1]);
                    h[nt][2] += elu_f(C[nt][2]); h[nt][3] += elu_f(C[nt][3]);
                }
            }

            // ---- heads (combined TN=8: nt0..3 = Wr1+br1, nt4..7 = Wc1+bc1) ----
            float C[8][4];
            #pragma unroll
            for (int nt = 0; nt < 4; nt++)
                initC(C[nt], *reinterpret_cast<const float2*>(S + OFF_BR1 + nt * 8 + 2 * q));
            #pragma unroll
            for (int nt = 0; nt < 4; nt++)
                initC(C[4 + nt], *reinterpret_cast<const float2*>(S + OFF_BC1 + nt * 8 + 2 * q));
            #pragma unroll
            for (int kt = 0; kt < 4; kt++) {
                unsigned a[4];
                pack2(h[2 * kt], h[2 * kt + 1], a);
                #pragma unroll
                for (int p = 0; p < 4; p++)
                    mma_pair(C[2*p], C[2*p+1], a, U + OFF_WHD, ((kt * 4 + p) * 32 + lane) * 4);
            }

            // regression: pred = elu(C[0..3]) @ Wr2 + br2
            {
                const float br2v = S[OFF_BR2];
                float s0 = 0.0f, s1 = 0.0f;
                #pragma unroll
                for (int nt = 0; nt < 4; nt++) {
                    int col = nt * 8 + 2 * q;
                    float2 w = *reinterpret_cast<const float2*>(S + OFF_WR2 + col);
                    s0 += elu_f(C[nt][0]) * w.x + elu_f(C[nt][1]) * w.y;
                    s1 += elu_f(C[nt][2]) * w.x + elu_f(C[nt][3]) * w.y;
                }
                s0 += __shfl_xor_sync(0xFFFFFFFFu, s0, 1);
                s0 += __shfl_xor_sync(0xFFFFFFFFu, s0, 2);
                s1 += __shfl_xor_sync(0xFFFFFFFFu, s1, 1);
                s1 += __shfl_xor_sync(0xFFFFFFFFu, s1, 2);
                if (q == 0) {
                    int r = row0 + mt * 16 + g;
                    if (r < B)     out[r]     = s0 + br2v;
                    if (r + 8 < B) out[r + 8] = s1 + br2v;
                }
            }

            // classification: logits = elu(C[4..7]) @ Wc2 + bc2
            {
                float4 bc2v = *reinterpret_cast<const float4*>(S + OFF_BC2);
                float4 v0 = make_float4(0.f, 0.f, 0.f, 0.f);
                float4 v1 = make_float4(0.f, 0.f, 0.f, 0.f);
                #pragma unroll
                for (int ntl = 0; ntl < 4; ntl++) {
                    const float* Cc = C[4 + ntl];
                    int col = ntl * 8 + 2 * q;
                    float e0 = elu_f(Cc[0]), e1 = elu_f(Cc[1]);
                    float e2 = elu_f(Cc[2]), e3 = elu_f(Cc[3]);
                    float4 w0 = *reinterpret_cast<const float4*>(S + OFF_WC2 + col * 4);
                    float4 w1 = *reinterpret_cast<const float4*>(S + OFF_WC2 + (col + 1) * 4);
                    v0.x += e0 * w0.x + e1 * w1.x; v0.y += e0 * w0.y + e1 * w1.y;
                    v0.z += e0 * w0.z + e1 * w1.z; v0.w += e0 * w0.w + e1 * w1.w;
                    v1.x += e2 * w0.x + e3 * w1.x; v1.y += e2 * w0.y + e3 * w1.y;
                    v1.z += e2 * w0.z + e3 * w1.z; v1.w += e2 * w0.w + e3 * w1.w;
                }
                #pragma unroll
                for (int d = 1; d <= 2; d <<= 1) {
                    v0.x += __shfl_xor_sync(0xFFFFFFFFu, v0.x, d);
                    v0.y += __shfl_xor_sync(0xFFFFFFFFu, v0.y, d);
                    v0.z += __shfl_xor_sync(0xFFFFFFFFu, v0.z, d);
                    v0.w += __shfl_xor_sync(0xFFFFFFFFu, v0.w, d);
                    v1.x += __shfl_xor_sync(0xFFFFFFFFu, v1.x, d);
                    v1.y += __shfl_xor_sync(0xFFFFFFFFu, v1.y, d);
                    v1.z += __shfl_xor_sync(0xFFFFFFFFu, v1.z, d);
                    v1.w += __shfl_xor_sync(0xFFFFFFFFu, v1.w, d);
                }
                if (q == 0) {
                    int r = row0 + mt * 16 + g;
                    if (r < B) {
                        float4 o = make_float4(v0.x + bc2v.x, v0.y + bc2v.y,
                                               v0.z + bc2v.z, v0.w + bc2v.w);
                        *reinterpret_cast<float4*>(out + B + 4LL * r) = o;
                    }
                    if (r + 8 < B) {
                        float4 o = make_float4(v1.x + bc2v.x, v1.y + bc2v.y,
                                               v1.z + bc2v.z, v1.w + bc2v.w);
                        *reinterpret_cast<float4*>(out + B + 4LL * (r + 8)) = o;
                    }
                }
            }
        }
        __syncwarp();
    }
}

extern "C" void kernel_launch(void* const* d_in, const int* in_sizes, int n_in,
                              void* d_out, int out_size) {
    const float* x    = (const float*)d_in[0];
    const float* Wsym = (const float*)d_in[1];
    const float* bsym = (const float*)d_in[2];
    const float* Win  = (const float*)d_in[3];
    const float* bin_ = (const float*)d_in[4];
    const float* W1   = (const float*)d_in[5];
    const float* b1   = (const float*)d_in[6];
    const float* W2   = (const float*)d_in[7];
    const float* b2   = (const float*)d_in[8];
    const float* W3   = (const float*)d_in[9];
    const float* b3   = (const float*)d_in[10];
    const float* Wr1  = (const float*)d_in[11];
    const float* br1  = (const float*)d_in[12];
    const float* Wr2  = (const float*)d_in[13];
    const float* br2  = (const float*)d_in[14];
    const float* Wc1  = (const float*)d_in[15];
    const float* bc1  = (const float*)d_in[16];
    const float* Wc2  = (const float*)d_in[17];
    const float* bc2  = (const float*)d_in[18];
    float* out = (float*)d_out;

    int B = in_sizes[0] / 10;

    cudaFuncSetAttribute(robustsym_mma_kernel,
                         cudaFuncAttributeMaxDynamicSharedMemorySize, SMEM_BYTES);

    robustsym_mma_kernel<<<GRID, THREADS, SMEM_BYTES>>>(
        x, Wsym, bsym, Win, bin_, W1, b1, W2, b2, W3, b3,
        Wr1, br1, Wr2, br2, Wc1, bc1, Wc2, bc2, out, B);
}